// round 3
// baseline (speedup 1.0000x reference)
#include <cuda_runtime.h>
#include <math.h>

#define NB 4
#define NN 512
#define TPB 256
#define PADW 65

typedef unsigned long long u64;

// scratch for precomputed h @ W1 halves (bias folded into hA)
__device__ float g_hA[NB * NN * 64];
__device__ float g_hB[NB * NN * 64];

__device__ __forceinline__ float gelu_exact(float v) {
    return 0.5f * v * (1.0f + erff(v * 0.70710678118654752440f));
}

__device__ __forceinline__ u64 pack2(float a, float b) {
    u64 r; asm("mov.b64 %0,{%1,%2};" : "=l"(r) : "f"(a), "f"(b)); return r;
}
__device__ __forceinline__ float2 unpack2(u64 v) {
    float2 f; asm("mov.b64 {%0,%1},%2;" : "=f"(f.x), "=f"(f.y) : "l"(v)); return f;
}
__device__ __forceinline__ void ffma2(u64& d, u64 a, u64 b) {
    asm("fma.rn.f32x2 %0,%1,%2,%0;" : "+l"(d) : "l"(a), "l"(b));
}

// ---------------------------------------------------------------------------
// Precompute hA = h @ e_w1[0:64] + e_b1,  hB = h @ e_w1[64:128]
// ---------------------------------------------------------------------------
__global__ void pre_kernel(const float* __restrict__ h,
                           const float* __restrict__ e_w1,
                           const float* __restrict__ e_b1) {
    int row = blockIdx.x;
    int c = threadIdx.x;
    __shared__ float hs[64];
    hs[c] = h[row * 64 + c];
    __syncthreads();
    float a = e_b1[c];
    float bacc = 0.f;
#pragma unroll
    for (int k = 0; k < 64; k++) {
        float hv = hs[k];
        a    += hv * e_w1[k * 64 + c];
        bacc += hv * e_w1[(64 + k) * 64 + c];
    }
    g_hA[row * 64 + c] = a;
    g_hB[row * 64 + c] = bacc;
}

// 64x64 GEMM step for 2 edges x 32 cols per thread, packed f32x2.
// Weights read via broadcast LDG (L1-resident); activations from padded smem.
__device__ __forceinline__ void gemm64_2e(u64* acc, const float* __restrict__ W,
                                          const float* mst,
                                          int e0, int e1, int cb) {
    const float4* __restrict__ Wv = reinterpret_cast<const float4*>(W + cb);
#pragma unroll 4
    for (int k = 0; k < 64; k++) {
        float a0 = mst[e0 * PADW + k];
        float a1 = mst[e1 * PADW + k];
        u64 pa0 = pack2(a0, a0);
        u64 pa1 = pack2(a1, a1);
#pragma unroll
        for (int q = 0; q < 8; q++) {
            float4 wv = __ldg(Wv + k * 16 + q);
            u64 w0 = pack2(wv.x, wv.y);
            u64 w1 = pack2(wv.z, wv.w);
            ffma2(acc[2 * q],      pa0, w0);
            ffma2(acc[2 * q + 1],  pa0, w1);
            ffma2(acc[16 + 2 * q], pa1, w0);
            ffma2(acc[17 + 2 * q], pa1, w1);
        }
    }
}

// ---------------------------------------------------------------------------
// Fused edge-MLP + aggregation + node-MLP + LayerNorm + coord update.
// One block per (b,i). 256 threads, 2 CTAs/SM. 2 tiles of 256 edges.
// Thread owns edges (tid&127, +128) and output cols [32*(tid>>7), +32).
// ---------------------------------------------------------------------------
__global__ void __launch_bounds__(TPB, 2) edge_kernel(
    const float* __restrict__ x,
    const float* __restrict__ h,
    const float* __restrict__ e_w1,
    const float* __restrict__ e_w2, const float* __restrict__ e_b2,
    const float* __restrict__ e_w3, const float* __restrict__ e_b3,
    const float* __restrict__ n_w1, const float* __restrict__ n_b1,
    const float* __restrict__ n_w2, const float* __restrict__ n_b2,
    const float* __restrict__ n_w3, const float* __restrict__ n_b3,
    const float* __restrict__ c_w1, const float* __restrict__ c_b1,
    const float* __restrict__ c_w2, const float* __restrict__ c_b2,
    const float* __restrict__ ln_g, const float* __restrict__ ln_b,
    float* __restrict__ out) {

    extern __shared__ float sm[];
    float* mst  = sm;                    // [256 * 65]
    float* w1cs = mst + 256 * PADW;      // 1024 (rbf rows of e_w1)
    float* cw2s = w1cs + 1024;           // 64
    float* eb2s = cw2s + 64;             // 64
    float* eb3s = eb2s + 64;             // 64
    float* cb1s = eb3s + 64;             // 64
    float* hAs  = cb1s + 64;             // 64
    float* mis  = hAs + 64;              // 64
    float* his  = mis + 64;              // 64
    float* bufA = his + 64;              // 64
    float* gpart= bufA + 64;             // 512
    float* red  = gpart + 512;           // 8

    const int tid = threadIdx.x;
    const int bi = blockIdx.x;
    const int b = bi >> 9;
    const int i = bi & 511;

    for (int idx = tid; idx < 1024; idx += TPB) w1cs[idx] = e_w1[128 * 64 + idx];
    if (tid < 64) {
        cw2s[tid] = c_w2[tid];
        eb2s[tid] = e_b2[tid];
        eb3s[tid] = e_b3[tid];
        cb1s[tid] = c_b1[tid];
        hAs[tid]  = g_hA[bi * 64 + tid];
        mis[tid]  = 0.f;
    }
    if (tid < 8) red[tid] = 0.f;
    __syncthreads();

    const float xi0 = x[bi * 3 + 0], xi1 = x[bi * 3 + 1], xi2 = x[bi * 3 + 2];
    const float cb2v = c_b2[0];

    const int e0 = tid & 127;
    const int e1 = e0 + 128;
    const int half = tid >> 7;
    const int cb = half * 32;

    for (int tile = 0; tile < 2; tile++) {
        const int j0 = tile * 256 + e0;
        const int j1 = j0 + 128;
        const int bj0 = b * 512 + j0;
        const int bj1 = b * 512 + j1;

        // geometry for both owned edges
        const float xa0 = x[bj0 * 3 + 0], xa1 = x[bj0 * 3 + 1], xa2 = x[bj0 * 3 + 2];
        const float xb0 = x[bj1 * 3 + 0], xb1 = x[bj1 * 3 + 1], xb2 = x[bj1 * 3 + 2];
        const float d00 = xi0 - xa0, d01 = xi1 - xa1, d02 = xi2 - xa2;
        const float d10 = xi0 - xb0, d11 = xi1 - xb1, d12 = xi2 - xb2;
        const float dist0 = sqrtf(d00 * d00 + d01 * d01 + d02 * d02 + 1e-8f);
        const float dist1 = sqrtf(d10 * d10 + d11 * d11 + d12 * d12 + 1e-8f);
        const bool mok0 = (j0 != i) && (dist0 <= 5.0f);
        const bool mok1 = (j1 != i) && (dist1 <= 5.0f);

        u64 acc[32];

        // ---- layer 1 init: hA_i + hB_j ----
        const float4* hb0 = reinterpret_cast<const float4*>(g_hB + (size_t)bj0 * 64 + cb);
        const float4* hb1 = reinterpret_cast<const float4*>(g_hB + (size_t)bj1 * 64 + cb);
#pragma unroll
        for (int q = 0; q < 8; q++) {
            float4 v0 = hb0[q];
            float4 v1 = hb1[q];
            float ha0 = hAs[cb + 4 * q + 0], ha1 = hAs[cb + 4 * q + 1];
            float ha2 = hAs[cb + 4 * q + 2], ha3 = hAs[cb + 4 * q + 3];
            acc[2 * q]      = pack2(ha0 + v0.x, ha1 + v0.y);
            acc[2 * q + 1]  = pack2(ha2 + v0.z, ha3 + v0.w);
            acc[16 + 2 * q] = pack2(ha0 + v1.x, ha1 + v1.y);
            acc[17 + 2 * q] = pack2(ha2 + v1.z, ha3 + v1.w);
        }
        // ---- + rbf @ W1c (rbf generated in-loop to cap registers) ----
#pragma unroll
        for (int r = 0; r < 16; r++) {
            float t0 = (dist0 - (float)r * (1.0f / 3.0f)) * 3.0f;
            float t1 = (dist1 - (float)r * (1.0f / 3.0f)) * 3.0f;
            float rv0 = expf(-0.5f * t0 * t0);
            float rv1 = expf(-0.5f * t1 * t1);
            u64 pr0 = pack2(rv0, rv0);
            u64 pr1 = pack2(rv1, rv1);
            const ulonglong2* wr = reinterpret_cast<const ulonglong2*>(w1cs + r * 64 + cb);
#pragma unroll
            for (int q = 0; q < 8; q++) {
                ulonglong2 wv = wr[q];
                ffma2(acc[2 * q],      pr0, wv.x);
                ffma2(acc[2 * q + 1],  pr0, wv.y);
                ffma2(acc[16 + 2 * q], pr1, wv.x);
                ffma2(acc[17 + 2 * q], pr1, wv.y);
            }
        }
        __syncthreads();   // prior tile's mst readers done
#pragma unroll
        for (int p = 0; p < 16; p++) {
            float2 f0 = unpack2(acc[p]);
            float2 f1 = unpack2(acc[16 + p]);
            mst[e0 * PADW + cb + 2 * p]     = gelu_exact(f0.x);
            mst[e0 * PADW + cb + 2 * p + 1] = gelu_exact(f0.y);
            mst[e1 * PADW + cb + 2 * p]     = gelu_exact(f1.x);
            mst[e1 * PADW + cb + 2 * p + 1] = gelu_exact(f1.y);
        }
        __syncthreads();

        // ---- layer 2 ----
#pragma unroll
        for (int p = 0; p < 16; p++) {
            u64 bp = pack2(eb2s[cb + 2 * p], eb2s[cb + 2 * p + 1]);
            acc[p] = bp; acc[16 + p] = bp;
        }
        gemm64_2e(acc, e_w2, mst, e0, e1, cb);
        __syncthreads();
#pragma unroll
        for (int p = 0; p < 16; p++) {
            float2 f0 = unpack2(acc[p]);
            float2 f1 = unpack2(acc[16 + p]);
            mst[e0 * PADW + cb + 2 * p]     = gelu_exact(f0.x);
            mst[e0 * PADW + cb + 2 * p + 1] = gelu_exact(f0.y);
            mst[e1 * PADW + cb + 2 * p]     = gelu_exact(f1.x);
            mst[e1 * PADW + cb + 2 * p + 1] = gelu_exact(f1.y);
        }
        __syncthreads();

        // ---- layer 3 -> masked m_ij ----
#pragma unroll
        for (int p = 0; p < 16; p++) {
            u64 bp = pack2(eb3s[cb + 2 * p], eb3s[cb + 2 * p + 1]);
            acc[p] = bp; acc[16 + p] = bp;
        }
        gemm64_2e(acc, e_w3, mst, e0, e1, cb);
        __syncthreads();
        {
            const float s0 = mok0 ? 1.f : 0.f;
            const float s1 = mok1 ? 1.f : 0.f;
#pragma unroll
            for (int p = 0; p < 16; p++) {
                float2 f0 = unpack2(acc[p]);
                float2 f1 = unpack2(acc[16 + p]);
                mst[e0 * PADW + cb + 2 * p]     = f0.x * s0;
                mst[e0 * PADW + cb + 2 * p + 1] = f0.y * s0;
                mst[e1 * PADW + cb + 2 * p]     = f1.x * s1;
                mst[e1 * PADW + cb + 2 * p + 1] = f1.y * s1;
            }
        }
        __syncthreads();

        // ---- coord gate GEMM ----
#pragma unroll
        for (int p = 0; p < 16; p++) {
            u64 bp = pack2(cb1s[cb + 2 * p], cb1s[cb + 2 * p + 1]);
            acc[p] = bp; acc[16 + p] = bp;
        }
        gemm64_2e(acc, c_w1, mst, e0, e1, cb);
        {
            float ps0 = 0.f, ps1 = 0.f;
#pragma unroll
            for (int p = 0; p < 16; p++) {
                float2 f0 = unpack2(acc[p]);
                float2 f1 = unpack2(acc[16 + p]);
                float wa = cw2s[cb + 2 * p], wb = cw2s[cb + 2 * p + 1];
                ps0 += gelu_exact(f0.x) * wa + gelu_exact(f0.y) * wb;
                ps1 += gelu_exact(f1.x) * wa + gelu_exact(f1.y) * wb;
            }
            gpart[e0 * 2 + half] = ps0;
            gpart[e1 * 2 + half] = ps1;
        }

        // ---- m_i partial reduction (reads masked mst) ----
        {
            int grp = tid >> 6, c = tid & 63;
            float s = 0.f;
#pragma unroll 8
            for (int r = grp * 64; r < grp * 64 + 64; r++) s += mst[r * PADW + c];
            atomicAdd(&mis[c], s);
        }
        __syncthreads();   // gpart ready

        // ---- finalize gate + coordinate reduction ----
        float p0 = 0.f, p1 = 0.f, p2 = 0.f, pc = 0.f;
        if (half == 0) {
            float g0 = gpart[e0 * 2] + gpart[e0 * 2 + 1] + cb2v;
            float g1 = gpart[e1 * 2] + gpart[e1 * 2 + 1] + cb2v;
            float gv0 = mok0 ? g0 : 0.f;
            float gv1 = mok1 ? g1 : 0.f;
            p0 = d00 * gv0 + d10 * gv1;
            p1 = d01 * gv0 + d11 * gv1;
            p2 = d02 * gv0 + d12 * gv1;
            pc = (mok0 ? 1.f : 0.f) + (mok1 ? 1.f : 0.f);
        }
#pragma unroll
        for (int o = 16; o > 0; o >>= 1) {
            p0 += __shfl_down_sync(0xffffffffu, p0, o);
            p1 += __shfl_down_sync(0xffffffffu, p1, o);
            p2 += __shfl_down_sync(0xffffffffu, p2, o);
            pc += __shfl_down_sync(0xffffffffu, pc, o);
        }
        if ((tid & 31) == 0) {
            atomicAdd(&red[0], p0);
            atomicAdd(&red[1], p1);
            atomicAdd(&red[2], p2);
            atomicAdd(&red[3], pc);
        }
        __syncthreads();
    }

    // ---------------- node MLP + LayerNorm (threads 0..63) ----------------
    if (tid < 64) his[tid] = h[bi * 64 + tid];
    __syncthreads();

    if (tid < 64) {
        float a = n_b1[tid];
#pragma unroll 4
        for (int k = 0; k < 64; k++) a += his[k] * n_w1[k * 64 + tid];
#pragma unroll 4
        for (int k = 0; k < 64; k++) a += mis[k] * n_w1[(64 + k) * 64 + tid];
        bufA[tid] = gelu_exact(a);
    }
    __syncthreads();

    float u2v = 0.f;
    if (tid < 64) {
        float a = n_b2[tid];
#pragma unroll 4
        for (int k = 0; k < 64; k++) a += bufA[k] * n_w2[k * 64 + tid];
        u2v = gelu_exact(a);
    }
    __syncthreads();
    if (tid < 64) bufA[tid] = u2v;
    __syncthreads();

    float hr = 0.f;
    if (tid < 64) {
        float a = n_b3[tid];
#pragma unroll 4
        for (int k = 0; k < 64; k++) a += bufA[k] * n_w3[k * 64 + tid];
        hr = his[tid] + a;
        float s1 = hr, s2 = hr * hr;
#pragma unroll
        for (int o = 16; o > 0; o >>= 1) {
            s1 += __shfl_down_sync(0xffffffffu, s1, o);
            s2 += __shfl_down_sync(0xffffffffu, s2, o);
        }
        if ((tid & 31) == 0) {
            atomicAdd(&red[4], s1);
            atomicAdd(&red[5], s2);
        }
    }
    __syncthreads();

    if (tid < 64) {
        float mu = red[4] * (1.0f / 64.0f);
        float var = red[5] * (1.0f / 64.0f) - mu * mu;
        float hn = (hr - mu) * rsqrtf(var + 1e-5f) * ln_g[tid] + ln_b[tid];
        out[NB * NN * 3 + bi * 64 + tid] = hn;
    }
    if (tid < 3) {
        float den = fmaxf(red[3], 1.0f);
        out[bi * 3 + tid] = x[bi * 3 + tid] + red[tid] / den;
    }
}

// ---------------------------------------------------------------------------
extern "C" void kernel_launch(void* const* d_in, const int* in_sizes, int n_in,
                              void* d_out, int out_size) {
    const float* x    = (const float*)d_in[0];
    const float* h    = (const float*)d_in[1];
    const float* e_w1 = (const float*)d_in[3];
    const float* e_b1 = (const float*)d_in[4];
    const float* e_w2 = (const float*)d_in[5];
    const float* e_b2 = (const float*)d_in[6];
    const float* e_w3 = (const float*)d_in[7];
    const float* e_b3 = (const float*)d_in[8];
    const float* n_w1 = (const float*)d_in[9];
    const float* n_b1 = (const float*)d_in[10];
    const float* n_w2 = (const float*)d_in[11];
    const float* n_b2 = (const float*)d_in[12];
    const float* n_w3 = (const float*)d_in[13];
    const float* n_b3 = (const float*)d_in[14];
    const float* c_w1 = (const float*)d_in[15];
    const float* c_b1 = (const float*)d_in[16];
    const float* c_w2 = (const float*)d_in[17];
    const float* c_b2 = (const float*)d_in[18];
    const float* ln_g = (const float*)d_in[19];
    const float* ln_b = (const float*)d_in[20];
    float* out = (float*)d_out;

    const size_t smem_floats = (size_t)256 * PADW + 1024 + 64 * 8 + 512 + 8;
    const size_t smem_bytes = smem_floats * sizeof(float);
    cudaFuncSetAttribute(edge_kernel, cudaFuncAttributeMaxDynamicSharedMemorySize,
                         (int)smem_bytes);

    pre_kernel<<<NB * NN, 64>>>(h, e_w1, e_b1);
    edge_kernel<<<NB * NN, TPB, smem_bytes>>>(
        x, h, e_w1, e_w2, e_b2, e_w3, e_b3,
        n_w1, n_b1, n_w2, n_b2, n_w3, n_b3,
        c_w1, c_b1, c_w2, c_b2, ln_g, ln_b, out);
}

// round 4
// speedup vs baseline: 1.1412x; 1.1412x over previous
#include <cuda_runtime.h>
#include <math.h>

#define NB 4
#define NN 512
#define TPB 256
#define PADW 65

typedef unsigned long long u64;

// scratch for precomputed h @ W1 halves (bias folded into hA)
__device__ float g_hA[NB * NN * 64];
__device__ float g_hB[NB * NN * 64];

__device__ __forceinline__ float gelu_exact(float v) {
    return 0.5f * v * (1.0f + erff(v * 0.70710678118654752440f));
}

__device__ __forceinline__ u64 pack2(float a, float b) {
    u64 r; asm("mov.b64 %0,{%1,%2};" : "=l"(r) : "f"(a), "f"(b)); return r;
}
__device__ __forceinline__ float2 unpack2(u64 v) {
    float2 f; asm("mov.b64 {%0,%1},%2;" : "=f"(f.x), "=f"(f.y) : "l"(v)); return f;
}
__device__ __forceinline__ void ffma2(u64& d, u64 a, u64 b) {
    asm("fma.rn.f32x2 %0,%1,%2,%0;" : "+l"(d) : "l"(a), "l"(b));
}

// ---------------------------------------------------------------------------
// Precompute hA = h @ e_w1[0:64] + e_b1,  hB = h @ e_w1[64:128]
// ---------------------------------------------------------------------------
__global__ void pre_kernel(const float* __restrict__ h,
                           const float* __restrict__ e_w1,
                           const float* __restrict__ e_b1) {
    int row = blockIdx.x;
    int c = threadIdx.x;
    __shared__ float hs[64];
    hs[c] = h[row * 64 + c];
    __syncthreads();
    float a = e_b1[c];
    float bacc = 0.f;
#pragma unroll
    for (int k = 0; k < 64; k++) {
        float hv = hs[k];
        a    += hv * e_w1[k * 64 + c];
        bacc += hv * e_w1[(64 + k) * 64 + c];
    }
    g_hA[row * 64 + c] = a;
    g_hB[row * 64 + c] = bacc;
}

// 64x64 GEMM step for 1 edge x 32 cols per thread, packed f32x2.
// Weights broadcast from smem; activations from padded smem.
__device__ __forceinline__ void gemm64_1e(u64* acc, const float* __restrict__ W,
                                          const float* __restrict__ mst,
                                          int e0, int cb) {
#pragma unroll 4
    for (int k = 0; k < 64; k++) {
        float a0 = mst[e0 * PADW + k];
        u64 pa0 = pack2(a0, a0);
        const ulonglong2* wr = reinterpret_cast<const ulonglong2*>(W + k * 64 + cb);
#pragma unroll
        for (int q = 0; q < 8; q++) {
            ulonglong2 wv = wr[q];
            ffma2(acc[2 * q],     pa0, wv.x);
            ffma2(acc[2 * q + 1], pa0, wv.y);
        }
    }
}

// ---------------------------------------------------------------------------
// Fused edge-MLP + aggregation + node-MLP + LayerNorm + coord update.
// One block per (b,i). 256 threads, 2 CTAs/SM. 4 sub-tiles of 128 edges.
// Thread owns edge (tid&127) and output cols [32*(tid>>7), +32).
// ---------------------------------------------------------------------------
__global__ void __launch_bounds__(TPB, 2) edge_kernel(
    const float* __restrict__ x,
    const float* __restrict__ h,
    const float* __restrict__ e_w1,
    const float* __restrict__ e_w2, const float* __restrict__ e_b2,
    const float* __restrict__ e_w3, const float* __restrict__ e_b3,
    const float* __restrict__ n_w1, const float* __restrict__ n_b1,
    const float* __restrict__ n_w2, const float* __restrict__ n_b2,
    const float* __restrict__ n_w3, const float* __restrict__ n_b3,
    const float* __restrict__ c_w1, const float* __restrict__ c_b1,
    const float* __restrict__ c_w2, const float* __restrict__ c_b2,
    const float* __restrict__ ln_g, const float* __restrict__ ln_b,
    float* __restrict__ out) {

    extern __shared__ float sm[];
    float* mst  = sm;                    // [128 * 65]
    float* w2s  = mst + 128 * PADW;      // 4096
    float* w3s  = w2s + 4096;            // 4096
    float* cw1s = w3s + 4096;            // 4096
    float* w1cs = cw1s + 4096;           // 1024
    float* cw2s = w1cs + 1024;           // 64
    float* eb2s = cw2s + 64;             // 64
    float* eb3s = eb2s + 64;             // 64
    float* cb1s = eb3s + 64;             // 64
    float* hAs  = cb1s + 64;             // 64
    float* mis  = hAs + 64;              // 64
    float* his  = mis + 64;              // 64
    float* bufA = his + 64;              // 64
    float* gpart= bufA + 64;             // 256
    float* red  = gpart + 256;           // 8

    const int tid = threadIdx.x;
    const int bi = blockIdx.x;
    const int b = bi >> 9;
    const int i = bi & 511;

    for (int idx = tid; idx < 4096; idx += TPB) {
        w2s[idx]  = e_w2[idx];
        w3s[idx]  = e_w3[idx];
        cw1s[idx] = c_w1[idx];
    }
    for (int idx = tid; idx < 1024; idx += TPB) w1cs[idx] = e_w1[128 * 64 + idx];
    if (tid < 64) {
        cw2s[tid] = c_w2[tid];
        eb2s[tid] = e_b2[tid];
        eb3s[tid] = e_b3[tid];
        cb1s[tid] = c_b1[tid];
        hAs[tid]  = g_hA[bi * 64 + tid];
        mis[tid]  = 0.f;
    }
    if (tid < 8) red[tid] = 0.f;
    __syncthreads();

    const float xi0 = x[bi * 3 + 0], xi1 = x[bi * 3 + 1], xi2 = x[bi * 3 + 2];
    const float cb2v = c_b2[0];

    const int e0 = tid & 127;
    const int half = tid >> 7;
    const int cb = half * 32;

    for (int st = 0; st < 4; st++) {
        const int j0 = st * 128 + e0;
        const int bj0 = b * 512 + j0;

        // geometry
        const float xa0 = x[bj0 * 3 + 0], xa1 = x[bj0 * 3 + 1], xa2 = x[bj0 * 3 + 2];
        const float d00 = xi0 - xa0, d01 = xi1 - xa1, d02 = xi2 - xa2;
        const float dist0 = sqrtf(d00 * d00 + d01 * d01 + d02 * d02 + 1e-8f);
        const bool mok0 = (j0 != i) && (dist0 <= 5.0f);

        u64 acc[16];

        // ---- layer 1 init: hA_i + hB_j ----
        const float4* hb0 = reinterpret_cast<const float4*>(g_hB + (size_t)bj0 * 64 + cb);
#pragma unroll
        for (int q = 0; q < 8; q++) {
            float4 v0 = hb0[q];
            acc[2 * q]     = pack2(hAs[cb + 4 * q + 0] + v0.x, hAs[cb + 4 * q + 1] + v0.y);
            acc[2 * q + 1] = pack2(hAs[cb + 4 * q + 2] + v0.z, hAs[cb + 4 * q + 3] + v0.w);
        }
        // ---- + rbf @ W1c ----
#pragma unroll
        for (int r = 0; r < 16; r++) {
            float t0 = (dist0 - (float)r * (1.0f / 3.0f)) * 3.0f;
            float rv0 = expf(-0.5f * t0 * t0);
            u64 pr0 = pack2(rv0, rv0);
            const ulonglong2* wr = reinterpret_cast<const ulonglong2*>(w1cs + r * 64 + cb);
#pragma unroll
            for (int q = 0; q < 8; q++) {
                ulonglong2 wv = wr[q];
                ffma2(acc[2 * q],     pr0, wv.x);
                ffma2(acc[2 * q + 1], pr0, wv.y);
            }
        }
        // previous sub-tile's mst readers finished at loop-end sync
#pragma unroll
        for (int p = 0; p < 16; p++) {
            float2 f0 = unpack2(acc[p]);
            mst[e0 * PADW + cb + 2 * p]     = gelu_exact(f0.x);
            mst[e0 * PADW + cb + 2 * p + 1] = gelu_exact(f0.y);
        }
        __syncthreads();

        // ---- layer 2 ----
#pragma unroll
        for (int p = 0; p < 16; p++)
            acc[p] = pack2(eb2s[cb + 2 * p], eb2s[cb + 2 * p + 1]);
        gemm64_1e(acc, w2s, mst, e0, cb);
        __syncthreads();
#pragma unroll
        for (int p = 0; p < 16; p++) {
            float2 f0 = unpack2(acc[p]);
            mst[e0 * PADW + cb + 2 * p]     = gelu_exact(f0.x);
            mst[e0 * PADW + cb + 2 * p + 1] = gelu_exact(f0.y);
        }
        __syncthreads();

        // ---- layer 3 -> masked m_ij ----
#pragma unroll
        for (int p = 0; p < 16; p++)
            acc[p] = pack2(eb3s[cb + 2 * p], eb3s[cb + 2 * p + 1]);
        gemm64_1e(acc, w3s, mst, e0, cb);
        __syncthreads();
        {
            const float s0 = mok0 ? 1.f : 0.f;
#pragma unroll
            for (int p = 0; p < 16; p++) {
                float2 f0 = unpack2(acc[p]);
                mst[e0 * PADW + cb + 2 * p]     = f0.x * s0;
                mst[e0 * PADW + cb + 2 * p + 1] = f0.y * s0;
            }
        }
        __syncthreads();

        // ---- coord gate GEMM ----
#pragma unroll
        for (int p = 0; p < 16; p++)
            acc[p] = pack2(cb1s[cb + 2 * p], cb1s[cb + 2 * p + 1]);
        gemm64_1e(acc, cw1s, mst, e0, cb);
        {
            float ps0 = 0.f;
#pragma unroll
            for (int p = 0; p < 16; p++) {
                float2 f0 = unpack2(acc[p]);
                ps0 += gelu_exact(f0.x) * cw2s[cb + 2 * p]
                     + gelu_exact(f0.y) * cw2s[cb + 2 * p + 1];
            }
            gpart[e0 * 2 + half] = ps0;
        }

        // ---- m_i partial reduction over this sub-tile's 128 rows ----
        {
            int grp = tid >> 6, c = tid & 63;
            float s = 0.f;
#pragma unroll 8
            for (int r = grp * 32; r < grp * 32 + 32; r++) s += mst[r * PADW + c];
            atomicAdd(&mis[c], s);
        }
        __syncthreads();   // gpart ready

        // ---- finalize gate + coordinate reduction ----
        float p0 = 0.f, p1 = 0.f, p2 = 0.f, pc = 0.f;
        if (half == 0) {
            float g0 = gpart[e0 * 2] + gpart[e0 * 2 + 1] + cb2v;
            float gv0 = mok0 ? g0 : 0.f;
            p0 = d00 * gv0;
            p1 = d01 * gv0;
            p2 = d02 * gv0;
            pc = mok0 ? 1.f : 0.f;
        }
#pragma unroll
        for (int o = 16; o > 0; o >>= 1) {
            p0 += __shfl_down_sync(0xffffffffu, p0, o);
            p1 += __shfl_down_sync(0xffffffffu, p1, o);
            p2 += __shfl_down_sync(0xffffffffu, p2, o);
            pc += __shfl_down_sync(0xffffffffu, pc, o);
        }
        if ((tid & 31) == 0 && half == 0) {
            atomicAdd(&red[0], p0);
            atomicAdd(&red[1], p1);
            atomicAdd(&red[2], p2);
            atomicAdd(&red[3], pc);
        }
        __syncthreads();   // mst free for next sub-tile
    }

    // ---------------- node MLP + LayerNorm (threads 0..63) ----------------
    if (tid < 64) his[tid] = h[bi * 64 + tid];
    __syncthreads();

    if (tid < 64) {
        float a = n_b1[tid];
#pragma unroll 4
        for (int k = 0; k < 64; k++) a += his[k] * n_w1[k * 64 + tid];
#pragma unroll 4
        for (int k = 0; k < 64; k++) a += mis[k] * n_w1[(64 + k) * 64 + tid];
        bufA[tid] = gelu_exact(a);
    }
    __syncthreads();

    float u2v = 0.f;
    if (tid < 64) {
        float a = n_b2[tid];
#pragma unroll 4
        for (int k = 0; k < 64; k++) a += bufA[k] * n_w2[k * 64 + tid];
        u2v = gelu_exact(a);
    }
    __syncthreads();
    if (tid < 64) bufA[tid] = u2v;
    __syncthreads();

    float hr = 0.f;
    if (tid < 64) {
        float a = n_b3[tid];
#pragma unroll 4
        for (int k = 0; k < 64; k++) a += bufA[k] * n_w3[k * 64 + tid];
        hr = his[tid] + a;
        float s1 = hr, s2 = hr * hr;
#pragma unroll
        for (int o = 16; o > 0; o >>= 1) {
            s1 += __shfl_down_sync(0xffffffffu, s1, o);
            s2 += __shfl_down_sync(0xffffffffu, s2, o);
        }
        if ((tid & 31) == 0) {
            atomicAdd(&red[4], s1);
            atomicAdd(&red[5], s2);
        }
    }
    __syncthreads();

    if (tid < 64) {
        float mu = red[4] * (1.0f / 64.0f);
        float var = red[5] * (1.0f / 64.0f) - mu * mu;
        float hn = (hr - mu) * rsqrtf(var + 1e-5f) * ln_g[tid] + ln_b[tid];
        out[NB * NN * 3 + bi * 64 + tid] = hn;
    }
    if (tid < 3) {
        float den = fmaxf(red[3], 1.0f);
        out[bi * 3 + tid] = x[bi * 3 + tid] + red[tid] / den;
    }
}

// ---------------------------------------------------------------------------
extern "C" void kernel_launch(void* const* d_in, const int* in_sizes, int n_in,
                              void* d_out, int out_size) {
    const float* x    = (const float*)d_in[0];
    const float* h    = (const float*)d_in[1];
    const float* e_w1 = (const float*)d_in[3];
    const float* e_b1 = (const float*)d_in[4];
    const float* e_w2 = (const float*)d_in[5];
    const float* e_b2 = (const float*)d_in[6];
    const float* e_w3 = (const float*)d_in[7];
    const float* e_b3 = (const float*)d_in[8];
    const float* n_w1 = (const float*)d_in[9];
    const float* n_b1 = (const float*)d_in[10];
    const float* n_w2 = (const float*)d_in[11];
    const float* n_b2 = (const float*)d_in[12];
    const float* n_w3 = (const float*)d_in[13];
    const float* n_b3 = (const float*)d_in[14];
    const float* c_w1 = (const float*)d_in[15];
    const float* c_b1 = (const float*)d_in[16];
    const float* c_w2 = (const float*)d_in[17];
    const float* c_b2 = (const float*)d_in[18];
    const float* ln_g = (const float*)d_in[19];
    const float* ln_b = (const float*)d_in[20];
    float* out = (float*)d_out;

    const size_t smem_floats = (size_t)128 * PADW + 4096 * 3 + 1024
                             + 64 * 8 + 256 + 8;
    const size_t smem_bytes = smem_floats * sizeof(float);
    cudaFuncSetAttribute(edge_kernel, cudaFuncAttributeMaxDynamicSharedMemorySize,
                         (int)smem_bytes);

    pre_kernel<<<NB * NN, 64>>>(h, e_w1, e_b1);
    edge_kernel<<<NB * NN, TPB, smem_bytes>>>(
        x, h, e_w1, e_w2, e_b2, e_w3, e_b3,
        n_w1, n_b1, n_w2, n_b2, n_w3, n_b3,
        c_w1, c_b1, c_w2, c_b2, ln_g, ln_b, out);
}

// round 5
// speedup vs baseline: 1.9586x; 1.7164x over previous
#include <cuda_runtime.h>
#include <math.h>

#define NB 4
#define NN 512
#define TPB 256
#define PADW 65

typedef unsigned long long u64;

// precomputed: h @ W1 halves, fused gate weights
__device__ float g_hA[NB * NN * 64];
__device__ float g_hB[NB * NN * 64];
__device__ float g_W23[64 * 64];
__device__ float g_b23[64];

__device__ __forceinline__ float gelu_exact(float v) {
    return 0.5f * v * (1.0f + erff(v * 0.70710678118654752440f));
}

__device__ __forceinline__ u64 pack2(float a, float b) {
    u64 r; asm("mov.b64 %0,{%1,%2};" : "=l"(r) : "f"(a), "f"(b)); return r;
}
__device__ __forceinline__ float2 unpack2(u64 v) {
    float2 f; asm("mov.b64 {%0,%1},%2;" : "=f"(f.x), "=f"(f.y) : "l"(v)); return f;
}
__device__ __forceinline__ void ffma2(u64& d, u64 a, u64 b) {
    asm("fma.rn.f32x2 %0,%1,%2,%0;" : "+l"(d) : "l"(a), "l"(b));
}

// ---------------------------------------------------------------------------
// Precompute hA = h @ e_w1[0:64] + e_b1,  hB = h @ e_w1[64:128]
// ---------------------------------------------------------------------------
__global__ void pre_kernel(const float* __restrict__ h,
                           const float* __restrict__ e_w1,
                           const float* __restrict__ e_b1) {
    int row = blockIdx.x;
    int c = threadIdx.x;
    __shared__ float hs[64];
    hs[c] = h[row * 64 + c];
    __syncthreads();
    float a = e_b1[c];
    float bacc = 0.f;
#pragma unroll
    for (int k = 0; k < 64; k++) {
        float hv = hs[k];
        a    += hv * e_w1[k * 64 + c];
        bacc += hv * e_w1[(64 + k) * 64 + c];
    }
    g_hA[row * 64 + c] = a;
    g_hB[row * 64 + c] = bacc;
}

// ---------------------------------------------------------------------------
// Precompute W23 = e_w3 @ c_w1 (64x64), b23 = e_b3 @ c_w1 + c_b1
// ---------------------------------------------------------------------------
__global__ void fuse_kernel(const float* __restrict__ e_w3,
                            const float* __restrict__ e_b3,
                            const float* __restrict__ c_w1,
                            const float* __restrict__ c_b1) {
    int idx = blockIdx.x * 256 + threadIdx.x;   // 0..4095
    int k = idx >> 6, c = idx & 63;
    float s = 0.f;
#pragma unroll 8
    for (int m = 0; m < 64; m++) s += e_w3[k * 64 + m] * c_w1[m * 64 + c];
    g_W23[idx] = s;
    if (idx < 64) {
        float bv = c_b1[idx];
#pragma unroll 8
        for (int m = 0; m < 64; m++) bv += e_b3[m] * c_w1[m * 64 + idx];
        g_b23[idx] = bv;
    }
}

// 64x64 GEMM step, 2 edges x 16 cols per thread, packed f32x2.
// Weights broadcast from smem (warp-uniform), activations from padded smem.
__device__ __forceinline__ void gemm2e16(u64* acc, const float* __restrict__ W,
                                         const float* __restrict__ mst,
                                         int e0, int e1, int cb) {
#pragma unroll 4
    for (int k = 0; k < 64; k++) {
        float a0 = mst[e0 * PADW + k];
        float a1 = mst[e1 * PADW + k];
        u64 pa0 = pack2(a0, a0);
        u64 pa1 = pack2(a1, a1);
        const ulonglong2* wr = reinterpret_cast<const ulonglong2*>(W + k * 64 + cb);
#pragma unroll
        for (int q = 0; q < 4; q++) {
            ulonglong2 wv = wr[q];
            ffma2(acc[2 * q],     pa0, wv.x);
            ffma2(acc[2 * q + 1], pa0, wv.y);
            ffma2(acc[8 + 2 * q], pa1, wv.x);
            ffma2(acc[9 + 2 * q], pa1, wv.y);
        }
    }
}

// ---------------------------------------------------------------------------
// Fused EGNN layer. One block per (b,i). 256 threads, 2 CTAs/SM.
// 4 sub-tiles of 128 edges; thread owns edges (tid&63, +64), cols [16*(tid>>6),+16).
// Per edge: layer1 (rbf GEMM + adds), layer2 (64x64), fused gate (64x64).
// Layer-3 hoisted out of the edge loop via W23/b23 and post-aggregation matvec.
// ---------------------------------------------------------------------------
__global__ void __launch_bounds__(TPB, 2) edge_kernel(
    const float* __restrict__ x,
    const float* __restrict__ h,
    const float* __restrict__ e_w1,
    const float* __restrict__ e_w2, const float* __restrict__ e_b2,
    const float* __restrict__ e_w3, const float* __restrict__ e_b3,
    const float* __restrict__ n_w1, const float* __restrict__ n_b1,
    const float* __restrict__ n_w2, const float* __restrict__ n_b2,
    const float* __restrict__ n_w3, const float* __restrict__ n_b3,
    const float* __restrict__ c_w2, const float* __restrict__ c_b2,
    const float* __restrict__ ln_g, const float* __restrict__ ln_b,
    float* __restrict__ out) {

    extern __shared__ float sm[];
    float* mst  = sm;                    // [128 * 65]
    float* w2s  = mst + 128 * PADW;      // 4096
    float* w23s = w2s + 4096;            // 4096
    float* w1cs = w23s + 4096;           // 1024
    float* cw2s = w1cs + 1024;           // 64
    float* eb2s = cw2s + 64;             // 64
    float* b23s = eb2s + 64;             // 64
    float* hAs  = b23s + 64;             // 64
    float* mis  = hAs + 64;              // 64  (S = sum of masked a2)
    float* his  = mis + 64;              // 64
    float* bufA = his + 64;              // 64
    float* gpart= bufA + 64;             // 512 (gate partials; reused as m_i)
    float* red  = gpart + 512;           // 8

    const int tid = threadIdx.x;
    const int bi = blockIdx.x;
    const int b = bi >> 9;
    const int i = bi & 511;

    for (int idx = tid; idx < 4096; idx += TPB) {
        w2s[idx]  = e_w2[idx];
        w23s[idx] = g_W23[idx];
    }
    for (int idx = tid; idx < 1024; idx += TPB) w1cs[idx] = e_w1[128 * 64 + idx];
    if (tid < 64) {
        cw2s[tid] = c_w2[tid];
        eb2s[tid] = e_b2[tid];
        b23s[tid] = g_b23[tid];
        hAs[tid]  = g_hA[bi * 64 + tid];
        mis[tid]  = 0.f;
    }
    if (tid < 8) red[tid] = 0.f;
    __syncthreads();

    const float xi0 = x[bi * 3 + 0], xi1 = x[bi * 3 + 1], xi2 = x[bi * 3 + 2];
    const float cb2v = c_b2[0];

    const int e0 = tid & 63;
    const int e1 = e0 + 64;
    const int cg = tid >> 6;
    const int cb = cg * 16;

    for (int st = 0; st < 4; st++) {
        const int j0 = st * 128 + e0;
        const int j1 = j0 + 64;
        const int bj0 = b * 512 + j0;
        const int bj1 = b * 512 + j1;

        // geometry for both owned edges
        const float xa0 = x[bj0 * 3 + 0], xa1 = x[bj0 * 3 + 1], xa2 = x[bj0 * 3 + 2];
        const float xb0 = x[bj1 * 3 + 0], xb1 = x[bj1 * 3 + 1], xb2 = x[bj1 * 3 + 2];
        const float d00 = xi0 - xa0, d01 = xi1 - xa1, d02 = xi2 - xa2;
        const float d10 = xi0 - xb0, d11 = xi1 - xb1, d12 = xi2 - xb2;
        const float dist0 = sqrtf(d00 * d00 + d01 * d01 + d02 * d02 + 1e-8f);
        const float dist1 = sqrtf(d10 * d10 + d11 * d11 + d12 * d12 + 1e-8f);
        const bool mok0 = (j0 != i) && (dist0 <= 5.0f);
        const bool mok1 = (j1 != i) && (dist1 <= 5.0f);

        u64 acc[16];

        // ---- layer 1: hA_i + hB_j + rbf @ W1c ----
        const float4* hb0 = reinterpret_cast<const float4*>(g_hB + (size_t)bj0 * 64 + cb);
        const float4* hb1 = reinterpret_cast<const float4*>(g_hB + (size_t)bj1 * 64 + cb);
#pragma unroll
        for (int q = 0; q < 4; q++) {
            float4 v0 = hb0[q];
            float4 v1 = hb1[q];
            float ha0 = hAs[cb + 4 * q + 0], ha1 = hAs[cb + 4 * q + 1];
            float ha2 = hAs[cb + 4 * q + 2], ha3 = hAs[cb + 4 * q + 3];
            acc[2 * q]     = pack2(ha0 + v0.x, ha1 + v0.y);
            acc[2 * q + 1] = pack2(ha2 + v0.z, ha3 + v0.w);
            acc[8 + 2 * q] = pack2(ha0 + v1.x, ha1 + v1.y);
            acc[9 + 2 * q] = pack2(ha2 + v1.z, ha3 + v1.w);
        }
#pragma unroll
        for (int r = 0; r < 16; r++) {
            float t0 = (dist0 - (float)r * (1.0f / 3.0f)) * 3.0f;
            float t1 = (dist1 - (float)r * (1.0f / 3.0f)) * 3.0f;
            float rv0 = expf(-0.5f * t0 * t0);
            float rv1 = expf(-0.5f * t1 * t1);
            u64 pr0 = pack2(rv0, rv0);
            u64 pr1 = pack2(rv1, rv1);
            const ulonglong2* wr = reinterpret_cast<const ulonglong2*>(w1cs + r * 64 + cb);
#pragma unroll
            for (int q = 0; q < 4; q++) {
                ulonglong2 wv = wr[q];
                ffma2(acc[2 * q],     pr0, wv.x);
                ffma2(acc[2 * q + 1], pr0, wv.y);
                ffma2(acc[8 + 2 * q], pr1, wv.x);
                ffma2(acc[9 + 2 * q], pr1, wv.y);
            }
        }
#pragma unroll
        for (int p = 0; p < 8; p++) {
            float2 f0 = unpack2(acc[p]);
            float2 f1 = unpack2(acc[8 + p]);
            mst[e0 * PADW + cb + 2 * p]     = gelu_exact(f0.x);
            mst[e0 * PADW + cb + 2 * p + 1] = gelu_exact(f0.y);
            mst[e1 * PADW + cb + 2 * p]     = gelu_exact(f1.x);
            mst[e1 * PADW + cb + 2 * p + 1] = gelu_exact(f1.y);
        }
        __syncthreads();   // (1) a1 ready

        // ---- layer 2 ----
#pragma unroll
        for (int p = 0; p < 8; p++) {
            u64 bp = pack2(eb2s[cb + 2 * p], eb2s[cb + 2 * p + 1]);
            acc[p] = bp; acc[8 + p] = bp;
        }
        gemm2e16(acc, w2s, mst, e0, e1, cb);
        __syncthreads();   // (2) a1 reads done
        {
            const float s0 = mok0 ? 1.f : 0.f;
            const float s1 = mok1 ? 1.f : 0.f;
#pragma unroll
            for (int p = 0; p < 8; p++) {
                float2 f0 = unpack2(acc[p]);
                float2 f1 = unpack2(acc[8 + p]);
                mst[e0 * PADW + cb + 2 * p]     = gelu_exact(f0.x) * s0;
                mst[e0 * PADW + cb + 2 * p + 1] = gelu_exact(f0.y) * s0;
                mst[e1 * PADW + cb + 2 * p]     = gelu_exact(f1.x) * s1;
                mst[e1 * PADW + cb + 2 * p + 1] = gelu_exact(f1.y) * s1;
            }
        }
        __syncthreads();   // (3) a2m ready

        // ---- fused gate: t = a2m @ W23 + b23; gpart = sum gelu(t)*c_w2 ----
#pragma unroll
        for (int p = 0; p < 8; p++) {
            u64 bp = pack2(b23s[cb + 2 * p], b23s[cb + 2 * p + 1]);
            acc[p] = bp; acc[8 + p] = bp;
        }
        gemm2e16(acc, w23s, mst, e0, e1, cb);
        {
            float ps0 = 0.f, ps1 = 0.f;
#pragma unroll
            for (int p = 0; p < 8; p++) {
                float2 f0 = unpack2(acc[p]);
                float2 f1 = unpack2(acc[8 + p]);
                float wa = cw2s[cb + 2 * p], wb = cw2s[cb + 2 * p + 1];
                ps0 += gelu_exact(f0.x) * wa + gelu_exact(f0.y) * wb;
                ps1 += gelu_exact(f1.x) * wa + gelu_exact(f1.y) * wb;
            }
            gpart[e0 * 4 + cg] = ps0;
            gpart[e1 * 4 + cg] = ps1;
        }

        // ---- S accumulation (masked a2) over this sub-tile's 128 rows ----
        {
            int c = tid & 63;
            float s = 0.f;
#pragma unroll 8
            for (int r = cg * 32; r < cg * 32 + 32; r++) s += mst[r * PADW + c];
            atomicAdd(&mis[c], s);
        }
        __syncthreads();   // (4) gpart ready, mst reads done

        // ---- finalize gate + coordinate reduction (cg==0 threads) ----
        float p0 = 0.f, p1 = 0.f, p2 = 0.f, pc = 0.f;
        if (cg == 0) {
            float g0 = gpart[e0 * 4] + gpart[e0 * 4 + 1] + gpart[e0 * 4 + 2]
                     + gpart[e0 * 4 + 3] + cb2v;
            float g1 = gpart[e1 * 4] + gpart[e1 * 4 + 1] + gpart[e1 * 4 + 2]
                     + gpart[e1 * 4 + 3] + cb2v;
            float gv0 = mok0 ? g0 : 0.f;
            float gv1 = mok1 ? g1 : 0.f;
            p0 = d00 * gv0 + d10 * gv1;
            p1 = d01 * gv0 + d11 * gv1;
            p2 = d02 * gv0 + d12 * gv1;
            pc = (mok0 ? 1.f : 0.f) + (mok1 ? 1.f : 0.f);
        }
#pragma unroll
        for (int o = 16; o > 0; o >>= 1) {
            p0 += __shfl_down_sync(0xffffffffu, p0, o);
            p1 += __shfl_down_sync(0xffffffffu, p1, o);
            p2 += __shfl_down_sync(0xffffffffu, p2, o);
            pc += __shfl_down_sync(0xffffffffu, pc, o);
        }
        if ((tid & 31) == 0 && cg == 0) {
            atomicAdd(&red[0], p0);
            atomicAdd(&red[1], p1);
            atomicAdd(&red[2], p2);
            atomicAdd(&red[3], pc);
        }
    }
    __syncthreads();   // loop done: red, mis complete

    // ---------------- m_i = S @ e_w3 + count * e_b3 ----------------
    if (tid < 64) {
        his[tid] = h[bi * 64 + tid];
        float cnt = red[3];
        float a = cnt * e_b3[tid];
#pragma unroll 4
        for (int k = 0; k < 64; k++) a += mis[k] * e_w3[k * 64 + tid];
        gpart[tid] = a;   // m_i
    }
    __syncthreads();

    // ---------------- node MLP + LayerNorm (threads 0..63) ----------------
    if (tid < 64) {
        float a = n_b1[tid];
#pragma unroll 4
        for (int k = 0; k < 64; k++) a += his[k] * n_w1[k * 64 + tid];
#pragma unroll 4
        for (int k = 0; k < 64; k++) a += gpart[k] * n_w1[(64 + k) * 64 + tid];
        bufA[tid] = gelu_exact(a);
    }
    __syncthreads();

    float u2v = 0.f;
    if (tid < 64) {
        float a = n_b2[tid];
#pragma unroll 4
        for (int k = 0; k < 64; k++) a += bufA[k] * n_w2[k * 64 + tid];
        u2v = gelu_exact(a);
    }
    __syncthreads();
    if (tid < 64) bufA[tid] = u2v;
    __syncthreads();

    float hr = 0.f;
    if (tid < 64) {
        float a = n_b3[tid];
#pragma unroll 4
        for (int k = 0; k < 64; k++) a += bufA[k] * n_w3[k * 64 + tid];
        hr = his[tid] + a;
        float s1 = hr, s2 = hr * hr;
#pragma unroll
        for (int o = 16; o > 0; o >>= 1) {
            s1 += __shfl_down_sync(0xffffffffu, s1, o);
            s2 += __shfl_down_sync(0xffffffffu, s2, o);
        }
        if ((tid & 31) == 0) {
            atomicAdd(&red[4], s1);
            atomicAdd(&red[5], s2);
        }
    }
    __syncthreads();

    if (tid < 64) {
        float mu = red[4] * (1.0f / 64.0f);
        float var = red[5] * (1.0f / 64.0f) - mu * mu;
        float hn = (hr - mu) * rsqrtf(var + 1e-5f) * ln_g[tid] + ln_b[tid];
        out[NB * NN * 3 + bi * 64 + tid] = hn;
    }
    if (tid < 3) {
        float den = fmaxf(red[3], 1.0f);
        out[bi * 3 + tid] = x[bi * 3 + tid] + red[tid] / den;
    }
}

// ---------------------------------------------------------------------------
extern "C" void kernel_launch(void* const* d_in, const int* in_sizes, int n_in,
                              void* d_out, int out_size) {
    const float* x    = (const float*)d_in[0];
    const float* h    = (const float*)d_in[1];
    const float* e_w1 = (const float*)d_in[3];
    const float* e_b1 = (const float*)d_in[4];
    const float* e_w2 = (const float*)d_in[5];
    const float* e_b2 = (const float*)d_in[6];
    const float* e_w3 = (const float*)d_in[7];
    const float* e_b3 = (const float*)d_in[8];
    const float* n_w1 = (const float*)d_in[9];
    const float* n_b1 = (const float*)d_in[10];
    const float* n_w2 = (const float*)d_in[11];
    const float* n_b2 = (const float*)d_in[12];
    const float* n_w3 = (const float*)d_in[13];
    const float* n_b3 = (const float*)d_in[14];
    const float* c_w1 = (const float*)d_in[15];
    const float* c_b1 = (const float*)d_in[16];
    const float* c_w2 = (const float*)d_in[17];
    const float* c_b2 = (const float*)d_in[18];
    const float* ln_g = (const float*)d_in[19];
    const float* ln_b = (const float*)d_in[20];
    float* out = (float*)d_out;

    const size_t smem_floats = (size_t)128 * PADW + 4096 * 2 + 1024
                             + 64 * 7 + 512 + 8;
    const size_t smem_bytes = smem_floats * sizeof(float);
    cudaFuncSetAttribute(edge_kernel, cudaFuncAttributeMaxDynamicSharedMemorySize,
                         (int)smem_bytes);

    pre_kernel<<<NB * NN, 64>>>(h, e_w1, e_b1);
    fuse_kernel<<<16, 256>>>(e_w3, e_b3, c_w1, c_b1);
    edge_kernel<<<NB * NN, TPB, smem_bytes>>>(
        x, h, e_w1, e_w2, e_b2, e_w3, e_b3,
        n_w1, n_b1, n_w2, n_b2, n_w3, n_b3,
        c_w2, c_b2, ln_g, ln_b, out);
}